// round 3
// baseline (speedup 1.0000x reference)
#include <cuda_runtime.h>
#include <math.h>

// ----------------------------------------------------------------------------
// SelfAttention: B=4, N=4096, d_in=d_new=1024, fp32.
//   Q/K/V = X*W + b      (NN gemm + bias)
//   S     = Q*K^T / 32   (NT gemm)
//   P     = softmax(S)   (row softmax, row len 4096)
//   O     = P*V          (NN gemm) -> d_out
// Round 2: fp32 SIMT tiled GEMM with register-staged prefetch.
// ----------------------------------------------------------------------------

#define BATCH 4
#define SEQ   4096
#define DIM   1024

#define BM 128
#define BN 128
#define BK 16
#define TM 8
#define TN 8
// 256 threads = (BM/TM)*(BN/TN)

// Scratch (allowed: __device__ globals, no runtime allocation)
__device__ float g_Q[(size_t)BATCH * SEQ * DIM];
__device__ float g_K[(size_t)BATCH * SEQ * DIM];
__device__ float g_V[(size_t)BATCH * SEQ * DIM];
__device__ float g_S[(size_t)BATCH * SEQ * SEQ];

// ----------------------------------------------------------------------------
// Tiled SGEMM with register-staged prefetch.
// C[m,n] = alpha * sum_k A[m,k] * Bmat(k,n) (+ bias[n])
//   TRANSB=false: Bmat(k,n) = B[k*N + n]   (B row-major K x N)
//   TRANSB=true : Bmat(k,n) = B[n*K + k]   (B row-major N x K, i.e. B^T)
// All dims are multiples of the tile sizes.
// ----------------------------------------------------------------------------
template <bool TRANSB, bool BIAS>
__global__ __launch_bounds__(256, 2)
void sgemm_kernel(const float* __restrict__ A,
                  const float* __restrict__ B,
                  const float* __restrict__ bias,
                  float* __restrict__ C,
                  int M, int N, int K, float alpha,
                  size_t sA, size_t sB, size_t sC)
{
    A += (size_t)blockIdx.z * sA;
    B += (size_t)blockIdx.z * sB;
    C += (size_t)blockIdx.z * sC;

    const int bm = blockIdx.y * BM;
    const int bn = blockIdx.x * BN;

    __shared__ float As[BK][BM];
    __shared__ float Bs[BK][BN];

    const int tid = threadIdx.x;
    const int tr  = tid >> 4;   // 0..15  (M direction)
    const int tc  = tid & 15;   // 0..15  (N direction)

    // A-tile loader: 128 rows x 16 cols, float4 along k, transposed store.
    const int aRow = tid >> 2;          // 0..63
    const int aCol = (tid & 3) << 2;    // 0,4,8,12
    // B-tile loader (NN): 16 rows x 128 cols, float4 along n.
    const int bRow = tid >> 5;          // 0..7
    const int bCol = (tid & 31) << 2;   // 0..124

    const float* aPtr0 = &A[(size_t)(bm + aRow)      * K + aCol];
    const float* aPtr1 = &A[(size_t)(bm + aRow + 64) * K + aCol];
    const float* bPtrT0 = TRANSB ? &B[(size_t)(bn + aRow)      * K + aCol] : nullptr;
    const float* bPtrT1 = TRANSB ? &B[(size_t)(bn + aRow + 64) * K + aCol] : nullptr;
    const float* bPtrN0 = TRANSB ? nullptr : &B[(size_t)bRow       * N + bn + bCol];
    const float* bPtrN1 = TRANSB ? nullptr : &B[(size_t)(bRow + 8) * N + bn + bCol];

    float acc[TM][TN];
    #pragma unroll
    for (int i = 0; i < TM; i++)
        #pragma unroll
        for (int j = 0; j < TN; j++) acc[i][j] = 0.0f;

    // ---- prefetch registers ----
    float4 pa0, pa1, pb0, pb1;

    // load tile 0
    pa0 = *(const float4*)&aPtr0[0];
    pa1 = *(const float4*)&aPtr1[0];
    if (TRANSB) {
        pb0 = *(const float4*)&bPtrT0[0];
        pb1 = *(const float4*)&bPtrT1[0];
    } else {
        pb0 = *(const float4*)&bPtrN0[0];
        pb1 = *(const float4*)&bPtrN1[0];
    }

    for (int kt = 0; kt < K; kt += BK) {
        // ---- store prefetched tile to smem ----
        As[aCol + 0][aRow]      = pa0.x;
        As[aCol + 1][aRow]      = pa0.y;
        As[aCol + 2][aRow]      = pa0.z;
        As[aCol + 3][aRow]      = pa0.w;
        As[aCol + 0][aRow + 64] = pa1.x;
        As[aCol + 1][aRow + 64] = pa1.y;
        As[aCol + 2][aRow + 64] = pa1.z;
        As[aCol + 3][aRow + 64] = pa1.w;
        if (TRANSB) {
            Bs[aCol + 0][aRow]      = pb0.x;
            Bs[aCol + 1][aRow]      = pb0.y;
            Bs[aCol + 2][aRow]      = pb0.z;
            Bs[aCol + 3][aRow]      = pb0.w;
            Bs[aCol + 0][aRow + 64] = pb1.x;
            Bs[aCol + 1][aRow + 64] = pb1.y;
            Bs[aCol + 2][aRow + 64] = pb1.z;
            Bs[aCol + 3][aRow + 64] = pb1.w;
        } else {
            *(float4*)&Bs[bRow][bCol]     = pb0;
            *(float4*)&Bs[bRow + 8][bCol] = pb1;
        }
        __syncthreads();

        // ---- prefetch next tile into registers (overlaps with compute) ----
        const int ktn = kt + BK;
        if (ktn < K) {
            pa0 = *(const float4*)&aPtr0[ktn];
            pa1 = *(const float4*)&aPtr1[ktn];
            if (TRANSB) {
                pb0 = *(const float4*)&bPtrT0[ktn];
                pb1 = *(const float4*)&bPtrT1[ktn];
            } else {
                pb0 = *(const float4*)&bPtrN0[(size_t)ktn * N];
                pb1 = *(const float4*)&bPtrN1[(size_t)ktn * N];
            }
        }

        // ---- compute current tile ----
        #pragma unroll
        for (int k = 0; k < BK; k++) {
            float ar[TM], br[TN];
            #pragma unroll
            for (int i = 0; i < TM; i += 4)
                *(float4*)&ar[i] = *(const float4*)&As[k][tr * TM + i];
            #pragma unroll
            for (int j = 0; j < TN; j += 4)
                *(float4*)&br[j] = *(const float4*)&Bs[k][tc * TN + j];
            #pragma unroll
            for (int i = 0; i < TM; i++)
                #pragma unroll
                for (int j = 0; j < TN; j++)
                    acc[i][j] = fmaf(ar[i], br[j], acc[i][j]);
        }
        __syncthreads();
    }

    // ---- epilogue ----
    #pragma unroll
    for (int i = 0; i < TM; i++) {
        const int row = bm + tr * TM + i;
        #pragma unroll
        for (int j = 0; j < TN; j += 4) {
            const int col = bn + tc * TN + j;
            float4 r;
            r.x = acc[i][j + 0] * alpha;
            r.y = acc[i][j + 1] * alpha;
            r.z = acc[i][j + 2] * alpha;
            r.w = acc[i][j + 3] * alpha;
            if (BIAS) {
                r.x += bias[col + 0];
                r.y += bias[col + 1];
                r.z += bias[col + 2];
                r.w += bias[col + 3];
            }
            *(float4*)&C[(size_t)row * N + col] = r;
        }
    }
}

// ----------------------------------------------------------------------------
// Row softmax: one block per row (row length SEQ=4096), 256 threads x 16 elems.
// ----------------------------------------------------------------------------
__global__ __launch_bounds__(256)
void softmax_kernel(float* __restrict__ S)
{
    float* p = S + (size_t)blockIdx.x * SEQ;
    const int t = threadIdx.x;

    float v[16];
    float m = -1e30f;
    #pragma unroll
    for (int i = 0; i < 16; i++) {
        v[i] = p[t + i * 256];
        m = fmaxf(m, v[i]);
    }
    // block max
    #pragma unroll
    for (int o = 16; o > 0; o >>= 1)
        m = fmaxf(m, __shfl_xor_sync(0xffffffffu, m, o));
    __shared__ float redm[8];
    __shared__ float reds[8];
    if ((t & 31) == 0) redm[t >> 5] = m;
    __syncthreads();
    float mb = redm[0];
    #pragma unroll
    for (int i = 1; i < 8; i++) mb = fmaxf(mb, redm[i]);

    float s = 0.0f;
    #pragma unroll
    for (int i = 0; i < 16; i++) {
        v[i] = expf(v[i] - mb);
        s += v[i];
    }
    #pragma unroll
    for (int o = 16; o > 0; o >>= 1)
        s += __shfl_xor_sync(0xffffffffu, s, o);
    if ((t & 31) == 0) reds[t >> 5] = s;
    __syncthreads();
    float sb = 0.0f;
    #pragma unroll
    for (int i = 0; i < 8; i++) sb += reds[i];

    const float inv = 1.0f / sb;
    #pragma unroll
    for (int i = 0; i < 16; i++)
        p[t + i * 256] = v[i] * inv;
}

// ----------------------------------------------------------------------------
// Launch
// ----------------------------------------------------------------------------
extern "C" void kernel_launch(void* const* d_in, const int* in_sizes, int n_in,
                              void* d_out, int out_size)
{
    const float* X  = (const float*)d_in[0];
    const float* Wq = (const float*)d_in[1];
    const float* Wk = (const float*)d_in[2];
    const float* Wv = (const float*)d_in[3];
    const float* bq = (const float*)d_in[4];
    const float* bk = (const float*)d_in[5];
    const float* bv = (const float*)d_in[6];
    float* O = (float*)d_out;

    float *Q, *K, *V, *S;
    cudaGetSymbolAddress((void**)&Q, g_Q);
    cudaGetSymbolAddress((void**)&K, g_K);
    cudaGetSymbolAddress((void**)&V, g_V);
    cudaGetSymbolAddress((void**)&S, g_S);

    const int MQKV = BATCH * SEQ;   // 16384
    const size_t strQKV = (size_t)SEQ * DIM;   // per-batch Q/K/V stride
    const size_t strS   = (size_t)SEQ * SEQ;   // per-batch scores stride
    const float scale = 1.0f / 32.0f;          // 1/sqrt(1024)

    // 1) QKV projections: [16384,1024] = [16384,1024] x [1024,1024] + bias
    {
        dim3 grid(DIM / BN, MQKV / BM, 1);
        sgemm_kernel<false, true><<<grid, 256>>>(X, Wq, bq, Q, MQKV, DIM, DIM, 1.0f, 0, 0, 0);
        sgemm_kernel<false, true><<<grid, 256>>>(X, Wk, bk, K, MQKV, DIM, DIM, 1.0f, 0, 0, 0);
        sgemm_kernel<false, true><<<grid, 256>>>(X, Wv, bv, V, MQKV, DIM, DIM, 1.0f, 0, 0, 0);
    }

    // 2) Scores: per batch S = Q * K^T * scale   [4096,4096]
    {
        dim3 grid(SEQ / BN, SEQ / BM, BATCH);
        sgemm_kernel<true, false><<<grid, 256>>>(Q, K, nullptr, S, SEQ, SEQ, DIM, scale,
                                                 strQKV, strQKV, strS);
    }

    // 3) Softmax over rows of S
    softmax_kernel<<<BATCH * SEQ, 256>>>(S);

    // 4) Output: per batch O = P * V   [4096,1024]
    {
        dim3 grid(DIM / BN, SEQ / BM, BATCH);
        sgemm_kernel<false, false><<<grid, 256>>>(S, V, nullptr, O, SEQ, DIM, SEQ, 1.0f,
                                                  strS, strQKV, strQKV);
    }
}

// round 7
// speedup vs baseline: 2.1567x; 2.1567x over previous
#include <cuda_runtime.h>
#include <cuda_bf16.h>
#include <cstdint>
#include <math.h>

// ============================================================================
// SelfAttention B=4, N=4096, d=1024 fp32.
// sm_100 (non-'a') target: tcgen05 unavailable -> warp-level tensor cores via
// ldmatrix + mma.sync.m16n8k16 bf16 with split-bf16 (3-product) fp32 accuracy.
//   x = hi + lo (bf16);  A*B ~= Ah*Bh + Ah*Bl + Al*Bh  (fp32 accumulate)
// Stages: QKV proj -> S=Q*K^T/32 -> softmax -> O=P*V.
// GEMM: block 128x128, 16 warps (warp tile 32x32), BK=64, double-buffered
// cp.async smem (padded stride, conflict-free ldmatrix).
// ============================================================================

#define BATCH 4
#define SEQ   4096
#define DIM   1024
#define MSEQ  (BATCH * SEQ)   // 16384

// ---------------- scratch (static device globals) ---------------------------
__device__ __nv_bfloat16 g_Xh[(size_t)MSEQ * DIM];
__device__ __nv_bfloat16 g_Xl[(size_t)MSEQ * DIM];
__device__ __nv_bfloat16 g_Wth[3][(size_t)DIM * DIM];
__device__ __nv_bfloat16 g_Wtl[3][(size_t)DIM * DIM];
__device__ __nv_bfloat16 g_Qh[(size_t)MSEQ * DIM];
__device__ __nv_bfloat16 g_Ql[(size_t)MSEQ * DIM];
__device__ __nv_bfloat16 g_Kh[(size_t)MSEQ * DIM];
__device__ __nv_bfloat16 g_Kl[(size_t)MSEQ * DIM];
__device__ float         g_Vf[(size_t)MSEQ * DIM];
__device__ __nv_bfloat16 g_Vth[(size_t)MSEQ * DIM];
__device__ __nv_bfloat16 g_Vtl[(size_t)MSEQ * DIM];
__device__ float         g_S [(size_t)BATCH * SEQ * SEQ];
__device__ __nv_bfloat16 g_Ph[(size_t)BATCH * SEQ * SEQ];
__device__ __nv_bfloat16 g_Pl[(size_t)BATCH * SEQ * SEQ];

// ---------------- helpers ----------------------------------------------------
__device__ __forceinline__ uint32_t smem_u32(const void* p) {
    uint32_t a;
    asm("{ .reg .u64 t; cvta.to.shared.u64 t, %1; cvt.u32.u64 %0, t; }"
        : "=r"(a) : "l"(p));
    return a;
}

__device__ __forceinline__ void ldsm4(uint32_t (&r)[4], uint32_t addr) {
    asm volatile("ldmatrix.sync.aligned.m8n8.x4.shared.b16 {%0,%1,%2,%3}, [%4];"
                 : "=r"(r[0]), "=r"(r[1]), "=r"(r[2]), "=r"(r[3]) : "r"(addr));
}

__device__ __forceinline__ void mma16816(float (&d)[4], const uint32_t (&a)[4],
                                         uint32_t b0, uint32_t b1) {
    asm volatile(
        "mma.sync.aligned.m16n8k16.row.col.f32.bf16.bf16.f32 "
        "{%0,%1,%2,%3}, {%4,%5,%6,%7}, {%8,%9}, {%0,%1,%2,%3};"
        : "+f"(d[0]), "+f"(d[1]), "+f"(d[2]), "+f"(d[3])
        : "r"(a[0]), "r"(a[1]), "r"(a[2]), "r"(a[3]), "r"(b0), "r"(b1));
}

__device__ __forceinline__ void split2(float v, __nv_bfloat16& h, __nv_bfloat16& l) {
    h = __float2bfloat16(v);
    l = __float2bfloat16(v - __bfloat162float(h));
}

// ---------------- GEMM (C = A * B^T over split pairs) -----------------------
// A[M,K] row-major (hi,lo), B[N,K] row-major (hi,lo).
// MODE 0: Cf = alpha*acc;  1: Cf = acc + bias[n];  2: (Ch,Cl)=split(acc+bias)
#define BKC   64
#define SROW  144                        // padded row stride bytes (72 bf16)
#define TILEB (128 * SROW)               // 18432 B per tile
#define OFF_AH 0
#define OFF_AL (1 * TILEB)
#define OFF_BH (2 * TILEB)
#define OFF_BL (3 * TILEB)
#define STAGE  (4 * TILEB)               // 73728 B
#define GSMEM  (2 * STAGE)               // 147456 B

// load one 128x64 bf16 tile (row-major, ldK elems) into padded smem via cp.async
__device__ __forceinline__ void load_tile(uint32_t dst, const __nv_bfloat16* g,
                                          int ldK, int tid) {
    #pragma unroll
    for (int i = 0; i < 2; i++) {
        int idx = i * 512 + tid;         // 1024 chunks of 16B
        int r = idx >> 3, c = idx & 7;
        uint32_t so = dst + (uint32_t)r * SROW + (uint32_t)c * 16;
        const __nv_bfloat16* src = g + (size_t)r * ldK + c * 8;
        asm volatile("cp.async.cg.shared.global [%0], [%1], 16;\n"
                     :: "r"(so), "l"(src) : "memory");
    }
}

template <int MODE>
__global__ void __launch_bounds__(512, 1)
gemm_mma(const __nv_bfloat16* __restrict__ Ah, const __nv_bfloat16* __restrict__ Al,
         const __nv_bfloat16* __restrict__ Bh, const __nv_bfloat16* __restrict__ Bl,
         const float* __restrict__ bias, float alpha,
         float* __restrict__ Cf, __nv_bfloat16* __restrict__ Ch,
         __nv_bfloat16* __restrict__ Cl,
         int N, int K, size_t sA, size_t sB, size_t sC)
{
    extern __shared__ char smem[];
    const uint32_t sb = smem_u32(smem);
    const int tid = threadIdx.x, wid = tid >> 5, lane = tid & 31;
    const int warpM = wid >> 2, warpN = wid & 3;     // 4x4 warps
    const int z = blockIdx.z;
    const size_t bm = (size_t)blockIdx.y * 128, bn = (size_t)blockIdx.x * 128;

    Ah += z * sA + bm * K;  Al += z * sA + bm * K;
    Bh += z * sB + bn * K;  Bl += z * sB + bn * K;
    const size_t zc = (size_t)z * sC;

    float acc[2][4][4];
    #pragma unroll
    for (int mt = 0; mt < 2; mt++)
        #pragma unroll
        for (int nt = 0; nt < 4; nt++)
            #pragma unroll
            for (int i = 0; i < 4; i++) acc[mt][nt][i] = 0.0f;

    const int nch = K / BKC;

    // prologue: chunk 0 -> stage 0
    {
        uint32_t s0 = sb;
        load_tile(s0 + OFF_AH, Ah, K, tid);
        load_tile(s0 + OFF_AL, Al, K, tid);
        load_tile(s0 + OFF_BH, Bh, K, tid);
        load_tile(s0 + OFF_BL, Bl, K, tid);
    }
    asm volatile("cp.async.commit_group;\n" ::: "memory");

    // ldmatrix lane offset: lanes 0-7 rows0-7 lo16B | 8-15 rows8-15 lo |
    //                       16-23 rows0-7 hi16B | 24-31 rows8-15 hi
    const uint32_t lmOff = (uint32_t)(lane & 15) * SROW + (uint32_t)((lane >> 4) << 4);

    for (int c = 0; c < nch; c++) {
        if (c + 1 < nch) {
            uint32_t s1 = sb + ((c + 1) & 1) * STAGE;
            const int kt = (c + 1) * BKC;
            load_tile(s1 + OFF_AH, Ah + kt, K, tid);
            load_tile(s1 + OFF_AL, Al + kt, K, tid);
            load_tile(s1 + OFF_BH, Bh + kt, K, tid);
            load_tile(s1 + OFF_BL, Bl + kt, K, tid);
            asm volatile("cp.async.commit_group;\n" ::: "memory");
            asm volatile("cp.async.wait_group 1;\n" ::: "memory");
        } else {
            asm volatile("cp.async.wait_group 0;\n" ::: "memory");
        }
        __syncthreads();

        const uint32_t st = sb + (c & 1) * STAGE;
        const uint32_t aBaseH = st + OFF_AH + (uint32_t)(warpM * 32) * SROW + lmOff;
        const uint32_t aBaseL = st + OFF_AL + (uint32_t)(warpM * 32) * SROW + lmOff;
        const uint32_t bBaseH = st + OFF_BH + (uint32_t)(warpN * 32) * SROW + lmOff;
        const uint32_t bBaseL = st + OFF_BL + (uint32_t)(warpN * 32) * SROW + lmOff;

        #pragma unroll
        for (int k16 = 0; k16 < BKC / 16; k16++) {
            const uint32_t kb = (uint32_t)k16 * 32;     // 16 bf16 = 32 B
            uint32_t ah[2][4], al[2][4], bhr[2][4], blr[2][4];
            ldsm4(ah[0], aBaseH + kb);
            ldsm4(ah[1], aBaseH + kb + 16 * SROW);
            ldsm4(al[0], aBaseL + kb);
            ldsm4(al[1], aBaseL + kb + 16 * SROW);
            ldsm4(bhr[0], bBaseH + kb);
            ldsm4(bhr[1], bBaseH + kb + 16 * SROW);
            ldsm4(blr[0], bBaseL + kb);
            ldsm4(blr[1], bBaseL + kb + 16 * SROW);
            // n8 tile nt: group g=nt/2, pair sel p=nt%2 -> {raw[g][p], raw[g][p+2]}
            #pragma unroll
            for (int mt = 0; mt < 2; mt++) {
                #pragma unroll
                for (int nt = 0; nt < 4; nt++) {
                    const int g = nt >> 1, p = nt & 1;
                    mma16816(acc[mt][nt], ah[mt], bhr[g][p], bhr[g][p + 2]);
                    mma16816(acc[mt][nt], ah[mt], blr[g][p], blr[g][p + 2]);
                    mma16816(acc[mt][nt], al[mt], bhr[g][p], bhr[g][p + 2]);
                }
            }
        }
        __syncthreads();
    }

    // ---- epilogue ----
    const int qr = lane >> 2, qc = (lane & 3) * 2;
    #pragma unroll
    for (int mt = 0; mt < 2; mt++) {
        #pragma unroll
        for (int nt = 0; nt < 4; nt++) {
            const size_t row0 = bm + warpM * 32 + mt * 16 + qr;
            const size_t col  = bn + warpN * 32 + nt * 8 + qc;
            #pragma unroll
            for (int h = 0; h < 2; h++) {       // h=0: row0, h=1: row0+8
                const size_t row = row0 + h * 8;
                float v0 = acc[mt][nt][2 * h + 0];
                float v1 = acc[mt][nt][2 * h + 1];
                if (MODE == 0) {
                    float2 r = make_float2(alpha * v0, alpha * v1);
                    *(float2*)&Cf[zc + row * N + col] = r;
                } else if (MODE == 1) {
                    float2 r = make_float2(v0 + __ldg(&bias[col]),
                                           v1 + __ldg(&bias[col + 1]));
                    *(float2*)&Cf[zc + row * N + col] = r;
                } else {
                    float w0 = v0 + __ldg(&bias[col]);
                    float w1 = v1 + __ldg(&bias[col + 1]);
                    __nv_bfloat16 h0, l0, h1, l1;
                    split2(w0, h0, l0);
                    split2(w1, h1, l1);
                    *(__nv_bfloat162*)&Ch[zc + row * N + col] =
                        __nv_bfloat162(h0, h1);
                    *(__nv_bfloat162*)&Cl[zc + row * N + col] =
                        __nv_bfloat162(l0, l1);
                }
            }
        }
    }
}

// ---------------- elementwise kernels ---------------------------------------
__global__ void __launch_bounds__(256) split_k(const float* __restrict__ in,
                                               __nv_bfloat16* __restrict__ oh,
                                               __nv_bfloat16* __restrict__ ol, size_t n)
{
    for (size_t i = (size_t)blockIdx.x * 256 + threadIdx.x; i < n;
         i += (size_t)gridDim.x * 256) {
        __nv_bfloat16 h, l;
        split2(in[i], h, l);
        oh[i] = h;  ol[i] = l;
    }
}

// out[c][r] = split(in[r][c]); in R x C, out C x R (per z slab)
__global__ void __launch_bounds__(256)
transpose_split_k(const float* __restrict__ in, __nv_bfloat16* __restrict__ oh,
                  __nv_bfloat16* __restrict__ ol, int R, int C, size_t sIn, size_t sOut)
{
    __shared__ float t[32][33];
    in += blockIdx.z * sIn;  oh += blockIdx.z * sOut;  ol += blockIdx.z * sOut;
    const int c0 = blockIdx.x * 32, r0 = blockIdx.y * 32;
    const int tx = threadIdx.x & 31, ty = threadIdx.x >> 5;  // 32x8
    #pragma unroll
    for (int j = 0; j < 32; j += 8)
        t[ty + j][tx] = in[(size_t)(r0 + ty + j) * C + c0 + tx];
    __syncthreads();
    #pragma unroll
    for (int j = 0; j < 32; j += 8) {
        float v = t[tx][ty + j];
        __nv_bfloat16 h, l;
        split2(v, h, l);
        size_t o = (size_t)(c0 + ty + j) * R + r0 + tx;
        oh[o] = h;  ol[o] = l;
    }
}

// row softmax over SEQ, emitting split-bf16 probabilities
__global__ void __launch_bounds__(256)
softmax_split_k(const float* __restrict__ S, __nv_bfloat16* __restrict__ Ph,
                __nv_bfloat16* __restrict__ Pl)
{
    const float* p = S + (size_t)blockIdx.x * SEQ;
    __nv_bfloat16* ph = Ph + (size_t)blockIdx.x * SEQ;
    __nv_bfloat16* pl = Pl + (size_t)blockIdx.x * SEQ;
    const int t = threadIdx.x;

    float v[16];
    float m = -1e30f;
    #pragma unroll
    for (int i = 0; i < 16; i++) { v[i] = p[t + i * 256]; m = fmaxf(m, v[i]); }
    #pragma unroll
    for (int o = 16; o > 0; o >>= 1) m = fmaxf(m, __shfl_xor_sync(~0u, m, o));
    __shared__ float redm[8], reds[8];
    if ((t & 31) == 0) redm[t >> 5] = m;
    __syncthreads();
    float mb = redm[0];
    #pragma unroll
    for (int i = 1; i < 8; i++) mb = fmaxf(mb, redm[i]);

    float s = 0.0f;
    #pragma unroll
    for (int i = 0; i < 16; i++) { v[i] = expf(v[i] - mb); s += v[i]; }
    #pragma unroll
    for (int o = 16; o > 0; o >>= 1) s += __shfl_xor_sync(~0u, s, o);
    if ((t & 31) == 0) reds[t >> 5] = s;
    __syncthreads();
    float sb = 0.0f;
    #pragma unroll
    for (int i = 0; i < 8; i++) sb += reds[i];

    const float inv = 1.0f / sb;
    #pragma unroll
    for (int i = 0; i < 16; i++) {
        __nv_bfloat16 h, l;
        split2(v[i] * inv, h, l);
        ph[t + i * 256] = h;
        pl[t + i * 256] = l;
    }
}

// ---------------- launch -----------------------------------------------------
extern "C" void kernel_launch(void* const* d_in, const int* in_sizes, int n_in,
                              void* d_out, int out_size)
{
    const float* X  = (const float*)d_in[0];
    const float* Wq = (const float*)d_in[1];
    const float* Wk = (const float*)d_in[2];
    const float* Wv = (const float*)d_in[3];
    const float* bq = (const float*)d_in[4];
    const float* bk = (const float*)d_in[5];
    const float* bv = (const float*)d_in[6];
    float* O = (float*)d_out;

    cudaFuncSetAttribute(gemm_mma<0>, cudaFuncAttributeMaxDynamicSharedMemorySize, GSMEM);
    cudaFuncSetAttribute(gemm_mma<1>, cudaFuncAttributeMaxDynamicSharedMemorySize, GSMEM);
    cudaFuncSetAttribute(gemm_mma<2>, cudaFuncAttributeMaxDynamicSharedMemorySize, GSMEM);

    __nv_bfloat16 *Xh, *Xl, *Wth, *Wtl, *Qh, *Ql, *Kh, *Kl, *Vth, *Vtl, *Ph, *Pl;
    float *Vf, *S;
    cudaGetSymbolAddress((void**)&Xh, g_Xh);   cudaGetSymbolAddress((void**)&Xl, g_Xl);
    cudaGetSymbolAddress((void**)&Wth, g_Wth); cudaGetSymbolAddress((void**)&Wtl, g_Wtl);
    cudaGetSymbolAddress((void**)&Qh, g_Qh);   cudaGetSymbolAddress((void**)&Ql, g_Ql);
    cudaGetSymbolAddress((void**)&Kh, g_Kh);   cudaGetSymbolAddress((void**)&Kl, g_Kl);
    cudaGetSymbolAddress((void**)&Vf, g_Vf);
    cudaGetSymbolAddress((void**)&Vth, g_Vth); cudaGetSymbolAddress((void**)&Vtl, g_Vtl);
    cudaGetSymbolAddress((void**)&S, g_S);
    cudaGetSymbolAddress((void**)&Ph, g_Ph);   cudaGetSymbolAddress((void**)&Pl, g_Pl);

    const size_t nX   = (size_t)MSEQ * DIM;
    const size_t strQ = (size_t)SEQ * DIM;
    const size_t strS = (size_t)SEQ * SEQ;
    const size_t strW = (size_t)DIM * DIM;

    // 1) split X; transpose+split W's
    split_k<<<4096, 256>>>(X, Xh, Xl, nX);
    {
        dim3 b(256), gW(DIM / 32, DIM / 32, 1);
        transpose_split_k<<<gW, b>>>(Wq, Wth + 0 * strW, Wtl + 0 * strW, DIM, DIM, 0, 0);
        transpose_split_k<<<gW, b>>>(Wk, Wth + 1 * strW, Wtl + 1 * strW, DIM, DIM, 0, 0);
        transpose_split_k<<<gW, b>>>(Wv, Wth + 2 * strW, Wtl + 2 * strW, DIM, DIM, 0, 0);
    }

    // 2) projections: M=16384, N=1024, K=1024
    {
        dim3 g(DIM / 128, MSEQ / 128, 1);
        gemm_mma<2><<<g, 512, GSMEM>>>(Xh, Xl, Wth + 0 * strW, Wtl + 0 * strW, bq, 1.0f,
                                       nullptr, Qh, Ql, DIM, DIM, 0, 0, 0);
        gemm_mma<2><<<g, 512, GSMEM>>>(Xh, Xl, Wth + 1 * strW, Wtl + 1 * strW, bk, 1.0f,
                                       nullptr, Kh, Kl, DIM, DIM, 0, 0, 0);
        gemm_mma<1><<<g, 512, GSMEM>>>(Xh, Xl, Wth + 2 * strW, Wtl + 2 * strW, bv, 1.0f,
                                       Vf, nullptr, nullptr, DIM, DIM, 0, 0, 0);
    }

    // 3) V^T split per batch: [4096 x 1024] -> [1024 x 4096]
    {
        dim3 b(256), gV(DIM / 32, SEQ / 32, BATCH);
        transpose_split_k<<<gV, b>>>(Vf, Vth, Vtl, SEQ, DIM, strQ, strQ);
    }

    // 4) scores: per batch S = Q*K^T / 32, M=N=4096, K=1024
    {
        dim3 g(SEQ / 128, SEQ / 128, BATCH);
        gemm_mma<0><<<g, 512, GSMEM>>>(Qh, Ql, Kh, Kl, nullptr, 1.0f / 32.0f,
                                       S, nullptr, nullptr, SEQ, DIM, strQ, strQ, strS);
    }

    // 5) softmax -> split P
    softmax_split_k<<<BATCH * SEQ, 256>>>(S, Ph, Pl);

    // 6) O = P*V: per batch M=4096, N=1024, K=4096
    {
        dim3 g(DIM / 128, SEQ / 128, BATCH);
        gemm_mma<0><<<g, 512, GSMEM>>>(Ph, Pl, Vth, Vtl, nullptr, 1.0f,
                                       O, nullptr, nullptr, DIM, SEQ, strS, strQ, strQ);
    }
}

// round 8
// speedup vs baseline: 2.1738x; 1.0079x over previous
#include <cuda_runtime.h>
#include <cuda_bf16.h>
#include <cstdint>
#include <math.h>

// ============================================================================
// SelfAttention B=4, N=4096, d=1024 fp32.
// sm_100 legacy tensor cores: ldmatrix + mma.sync.m16n8k16 bf16, split-bf16
// 3-product fp32 accuracy:  A*B ~= Ah*Bh + Ah*Bl + Al*Bh.
// Round 8: block 128x256, warp tile 32x64 (16 warps) -> 32.7 FLOP/smem-byte,
// smem crossbar and tensor pipe balanced (was smem-bound at 12 FLOP/B).
// ============================================================================

#define BATCH 4
#define SEQ   4096
#define DIM   1024
#define MSEQ  (BATCH * SEQ)   // 16384

// ---------------- scratch (static device globals) ---------------------------
__device__ __nv_bfloat16 g_Xh[(size_t)MSEQ * DIM];
__device__ __nv_bfloat16 g_Xl[(size_t)MSEQ * DIM];
__device__ __nv_bfloat16 g_Wth[3][(size_t)DIM * DIM];
__device__ __nv_bfloat16 g_Wtl[3][(size_t)DIM * DIM];
__device__ __nv_bfloat16 g_Qh[(size_t)MSEQ * DIM];
__device__ __nv_bfloat16 g_Ql[(size_t)MSEQ * DIM];
__device__ __nv_bfloat16 g_Kh[(size_t)MSEQ * DIM];
__device__ __nv_bfloat16 g_Kl[(size_t)MSEQ * DIM];
__device__ float         g_Vf[(size_t)MSEQ * DIM];
__device__ __nv_bfloat16 g_Vth[(size_t)MSEQ * DIM];
__device__ __nv_bfloat16 g_Vtl[(size_t)MSEQ * DIM];
__device__ float         g_S [(size_t)BATCH * SEQ * SEQ];
__device__ __nv_bfloat16 g_Ph[(size_t)BATCH * SEQ * SEQ];
__device__ __nv_bfloat16 g_Pl[(size_t)BATCH * SEQ * SEQ];

// ---------------- helpers ----------------------------------------------------
__device__ __forceinline__ uint32_t smem_u32(const void* p) {
    uint32_t a;
    asm("{ .reg .u64 t; cvta.to.shared.u64 t, %1; cvt.u32.u64 %0, t; }"
        : "=r"(a) : "l"(p));
    return a;
}

__device__ __forceinline__ void ldsm4(uint32_t (&r)[4], uint32_t addr) {
    asm volatile("ldmatrix.sync.aligned.m8n8.x4.shared.b16 {%0,%1,%2,%3}, [%4];"
                 : "=r"(r[0]), "=r"(r[1]), "=r"(r[2]), "=r"(r[3]) : "r"(addr));
}

__device__ __forceinline__ void mma16816(float (&d)[4], const uint32_t (&a)[4],
                                         uint32_t b0, uint32_t b1) {
    asm volatile(
        "mma.sync.aligned.m16n8k16.row.col.f32.bf16.bf16.f32 "
        "{%0,%1,%2,%3}, {%4,%5,%6,%7}, {%8,%9}, {%0,%1,%2,%3};"
        : "+f"(d[0]), "+f"(d[1]), "+f"(d[2]), "+f"(d[3])
        : "r"(a[0]), "r"(a[1]), "r"(a[2]), "r"(a[3]), "r"(b0), "r"(b1));
}

__device__ __forceinline__ void split2(float v, __nv_bfloat16& h, __nv_bfloat16& l) {
    h = __float2bfloat16(v);
    l = __float2bfloat16(v - __bfloat162float(h));
}

// ---------------- GEMM (C = A * B^T over split pairs) -----------------------
// A[M,K] row-major (hi,lo), B[N,K] row-major (hi,lo).
// Block 128(M) x 256(N), 16 warps in 4x4, warp tile 32x64, BK=64, 2 stages.
// MODE 0: Cf = alpha*acc;  1: Cf = acc + bias[n];  2: (Ch,Cl)=split(acc+bias)
#define BKC    64
#define SROW   144                        // padded row stride bytes (72 bf16)
#define TILE_A (128 * SROW)               // 18432 B
#define TILE_B (256 * SROW)               // 36864 B
#define OFF_AH 0
#define OFF_AL TILE_A
#define OFF_BH (2 * TILE_A)
#define OFF_BL (2 * TILE_A + TILE_B)
#define STAGE  (2 * TILE_A + 2 * TILE_B)  // 110592 B
#define GSMEM  (2 * STAGE)                // 221184 B

// load one ROWSx64 bf16 tile (row-major, ldK elems) into padded smem (512 thr)
template <int ROWS>
__device__ __forceinline__ void load_tile(uint32_t dst, const __nv_bfloat16* g,
                                          int ldK, int tid) {
    #pragma unroll
    for (int i = 0; i < ROWS * 8 / 512; i++) {
        int idx = i * 512 + tid;
        int r = idx >> 3, c = idx & 7;
        uint32_t so = dst + (uint32_t)r * SROW + (uint32_t)c * 16;
        const __nv_bfloat16* src = g + (size_t)r * ldK + c * 8;
        asm volatile("cp.async.cg.shared.global [%0], [%1], 16;\n"
                     :: "r"(so), "l"(src) : "memory");
    }
}

template <int MODE>
__global__ void __launch_bounds__(512, 1)
gemm_mma(const __nv_bfloat16* __restrict__ Ah, const __nv_bfloat16* __restrict__ Al,
         const __nv_bfloat16* __restrict__ Bh, const __nv_bfloat16* __restrict__ Bl,
         const float* __restrict__ bias, float alpha,
         float* __restrict__ Cf, __nv_bfloat16* __restrict__ Ch,
         __nv_bfloat16* __restrict__ Cl,
         int N, int K, size_t sA, size_t sB, size_t sC)
{
    extern __shared__ char smem[];
    const uint32_t sb = smem_u32(smem);
    const int tid = threadIdx.x, wid = tid >> 5, lane = tid & 31;
    const int warpM = wid >> 2, warpN = wid & 3;     // 4x4 warps
    const int z = blockIdx.z;
    const size_t bm = (size_t)blockIdx.y * 128, bn = (size_t)blockIdx.x * 256;

    Ah += z * sA + bm * K;  Al += z * sA + bm * K;
    Bh += z * sB + bn * K;  Bl += z * sB + bn * K;
    const size_t zc = (size_t)z * sC;

    float acc[2][8][4];
    #pragma unroll
    for (int mt = 0; mt < 2; mt++)
        #pragma unroll
        for (int nt = 0; nt < 8; nt++)
            #pragma unroll
            for (int i = 0; i < 4; i++) acc[mt][nt][i] = 0.0f;

    const int nch = K / BKC;

    // prologue: chunk 0 -> stage 0
    load_tile<128>(sb + OFF_AH, Ah, K, tid);
    load_tile<128>(sb + OFF_AL, Al, K, tid);
    load_tile<256>(sb + OFF_BH, Bh, K, tid);
    load_tile<256>(sb + OFF_BL, Bl, K, tid);
    asm volatile("cp.async.commit_group;\n" ::: "memory");

    // ldmatrix lane offset within a 16-row x 32B region
    const uint32_t lmOff = (uint32_t)(lane & 15) * SROW + (uint32_t)((lane >> 4) << 4);

    for (int c = 0; c < nch; c++) {
        if (c + 1 < nch) {
            const uint32_t s1 = sb + ((c + 1) & 1) * STAGE;
            const int kt = (c + 1) * BKC;
            load_tile<128>(s1 + OFF_AH, Ah + kt, K, tid);
            load_tile<128>(s1 + OFF_AL, Al + kt, K, tid);
            load_tile<256>(s1 + OFF_BH, Bh + kt, K, tid);
            load_tile<256>(s1 + OFF_BL, Bl + kt, K, tid);
            asm volatile("cp.async.commit_group;\n" ::: "memory");
            asm volatile("cp.async.wait_group 1;\n" ::: "memory");
        } else {
            asm volatile("cp.async.wait_group 0;\n" ::: "memory");
        }
        __syncthreads();

        const uint32_t st = sb + (c & 1) * STAGE;
        const uint32_t aBaseH = st + OFF_AH + (uint32_t)(warpM * 32) * SROW + lmOff;
        const uint32_t aBaseL = st + OFF_AL + (uint32_t)(warpM * 32) * SROW + lmOff;
        const uint32_t bBaseH = st + OFF_BH + (uint32_t)(warpN * 64) * SROW + lmOff;
        const uint32_t bBaseL = st + OFF_BL + (uint32_t)(warpN * 64) * SROW + lmOff;

        #pragma unroll
        for (int k16 = 0; k16 < BKC / 16; k16++) {
            const uint32_t kb = (uint32_t)k16 * 32;     // 16 bf16 = 32 B
            uint32_t ah[2][4], al[2][4];
            ldsm4(ah[0], aBaseH + kb);
            ldsm4(ah[1], aBaseH + kb + 16 * SROW);
            ldsm4(al[0], aBaseL + kb);
            ldsm4(al[1], aBaseL + kb + 16 * SROW);
            #pragma unroll
            for (int g = 0; g < 4; g++) {               // 16-col n-groups
                const uint32_t bo = kb + (uint32_t)(g * 16) * SROW;
                uint32_t bh[4], bl[4];
                ldsm4(bh, bBaseH + bo);
                ldsm4(bl, bBaseL + bo);
                #pragma unroll
                for (int mt = 0; mt < 2; mt++) {
                    #pragma unroll
                    for (int p = 0; p < 2; p++) {       // n8 within group
                        const int nt = g * 2 + p;
                        mma16816(acc[mt][nt], ah[mt], bh[p], bh[p + 2]);
                        mma16816(acc[mt][nt], ah[mt], bl[p], bl[p + 2]);
                        mma16816(acc[mt][nt], al[mt], bh[p], bh[p + 2]);
                    }
                }
            }
        }
        __syncthreads();
    }

    // ---- epilogue ----
    const int qr = lane >> 2, qc = (lane & 3) * 2;
    #pragma unroll
    for (int mt = 0; mt < 2; mt++) {
        #pragma unroll
        for (int nt = 0; nt < 8; nt++) {
            const size_t row0 = bm + warpM * 32 + mt * 16 + qr;
            const size_t col  = bn + warpN * 64 + nt * 8 + qc;
            #pragma unroll
            for (int h = 0; h < 2; h++) {       // h=0: row0, h=1: row0+8
                const size_t row = row0 + h * 8;
                float v0 = acc[mt][nt][2 * h + 0];
                float v1 = acc[mt][nt][2 * h + 1];
                if (MODE == 0) {
                    float2 r = make_float2(alpha * v0, alpha * v1);
                    *(float2*)&Cf[zc + row * N + col] = r;
                } else if (MODE == 1) {
                    float2 r = make_float2(v0 + __ldg(&bias[col]),
                                           v1 + __ldg(&bias[col + 1]));
                    *(float2*)&Cf[zc + row * N + col] = r;
                } else {
                    float w0 = v0 + __ldg(&bias[col]);
                    float w1 = v1 + __ldg(&bias[col + 1]);
                    __nv_bfloat16 h0, l0, h1, l1;
                    split2(w0, h0, l0);
                    split2(w1, h1, l1);
                    *(__nv_bfloat162*)&Ch[zc + row * N + col] =
                        __nv_bfloat162(h0, h1);
                    *(__nv_bfloat162*)&Cl[zc + row * N + col] =
                        __nv_bfloat162(l0, l1);
                }
            }
        }
    }
}

// ---------------- elementwise kernels ---------------------------------------
__global__ void __launch_bounds__(256) split_k(const float* __restrict__ in,
                                               __nv_bfloat16* __restrict__ oh,
                                               __nv_bfloat16* __restrict__ ol, size_t n)
{
    for (size_t i = (size_t)blockIdx.x * 256 + threadIdx.x; i < n;
         i += (size_t)gridDim.x * 256) {
        __nv_bfloat16 h, l;
        split2(in[i], h, l);
        oh[i] = h;  ol[i] = l;
    }
}

// out[c][r] = split(in[r][c]); in R x C, out C x R (per z slab)
__global__ void __launch_bounds__(256)
transpose_split_k(const float* __restrict__ in, __nv_bfloat16* __restrict__ oh,
                  __nv_bfloat16* __restrict__ ol, int R, int C, size_t sIn, size_t sOut)
{
    __shared__ float t[32][33];
    in += blockIdx.z * sIn;  oh += blockIdx.z * sOut;  ol += blockIdx.z * sOut;
    const int c0 = blockIdx.x * 32, r0 = blockIdx.y * 32;
    const int tx = threadIdx.x & 31, ty = threadIdx.x >> 5;  // 32x8
    #pragma unroll
    for (int j = 0; j < 32; j += 8)
        t[ty + j][tx] = in[(size_t)(r0 + ty + j) * C + c0 + tx];
    __syncthreads();
    #pragma unroll
    for (int j = 0; j < 32; j += 8) {
        float v = t[tx][ty + j];
        __nv_bfloat16 h, l;
        split2(v, h, l);
        size_t o = (size_t)(c0 + ty + j) * R + r0 + tx;
        oh[o] = h;  ol[o] = l;
    }
}

// row softmax over SEQ, emitting split-bf16 probabilities
__global__ void __launch_bounds__(256)
softmax_split_k(const float* __restrict__ S, __nv_bfloat16* __restrict__ Ph,
                __nv_bfloat16* __restrict__ Pl)
{
    const float* p = S + (size_t)blockIdx.x * SEQ;
    __nv_bfloat16* ph = Ph + (size_t)blockIdx.x * SEQ;
    __nv_bfloat16* pl = Pl + (size_t)blockIdx.x * SEQ;
    const int t = threadIdx.x;

    float v[16];
    float m = -1e30f;
    #pragma unroll
    for (int i = 0; i < 16; i++) { v[i] = p[t + i * 256]; m = fmaxf(m, v[i]); }
    #pragma unroll
    for (int o = 16; o > 0; o >>= 1) m = fmaxf(m, __shfl_xor_sync(~0u, m, o));
    __shared__ float redm[8], reds[8];
    if ((t & 31) == 0) redm[t >> 5] = m;
    __syncthreads();
    float mb = redm[0];
    #pragma unroll
    for (int i = 1; i < 8; i++) mb = fmaxf(mb, redm[i]);

    float s = 0.0f;
    #pragma unroll
    for (int i = 0; i < 16; i++) { v[i] = expf(v[i] - mb); s += v[i]; }
    #pragma unroll
    for (int o = 16; o > 0; o >>= 1) s += __shfl_xor_sync(~0u, s, o);
    if ((t & 31) == 0) reds[t >> 5] = s;
    __syncthreads();
    float sb = 0.0f;
    #pragma unroll
    for (int i = 0; i < 8; i++) sb += reds[i];

    const float inv = 1.0f / sb;
    #pragma unroll
    for (int i = 0; i < 16; i++) {
        __nv_bfloat16 h, l;
        split2(v[i] * inv, h, l);
        ph[t + i * 256] = h;
        pl[t + i * 256] = l;
    }
}

// ---------------- launch -----------------------------------------------------
extern "C" void kernel_launch(void* const* d_in, const int* in_sizes, int n_in,
                              void* d_out, int out_size)
{
    const float* X  = (const float*)d_in[0];
    const float* Wq = (const float*)d_in[1];
    const float* Wk = (const float*)d_in[2];
    const float* Wv = (const float*)d_in[3];
    const float* bq = (const float*)d_in[4];
    const float* bk = (const float*)d_in[5];
    const float* bv = (const float*)d_in[6];
    float* O = (float*)d_out;

    cudaFuncSetAttribute(gemm_mma<0>, cudaFuncAttributeMaxDynamicSharedMemorySize, GSMEM);
    cudaFuncSetAttribute(gemm_mma<1>, cudaFuncAttributeMaxDynamicSharedMemorySize, GSMEM);
    cudaFuncSetAttribute(gemm_mma<2>, cudaFuncAttributeMaxDynamicSharedMemorySize, GSMEM);

    __nv_bfloat16 *Xh, *Xl, *Wth, *Wtl, *Qh, *Ql, *Kh, *Kl, *Vth, *Vtl, *Ph, *Pl;
    float *Vf, *S;
    cudaGetSymbolAddress((void**)&Xh, g_Xh);   cudaGetSymbolAddress((void**)&Xl, g_Xl);
    cudaGetSymbolAddress((void**)&Wth, g_Wth); cudaGetSymbolAddress((void**)&Wtl, g_Wtl);
    cudaGetSymbolAddress((void**)&Qh, g_Qh);   cudaGetSymbolAddress((void**)&Ql, g_Ql);
    cudaGetSymbolAddress((void**)&Kh, g_Kh);   cudaGetSymbolAddress((void**)&Kl, g_Kl);
    cudaGetSymbolAddress((void**)&Vf, g_Vf);
    cudaGetSymbolAddress((void**)&Vth, g_Vth); cudaGetSymbolAddress((void**)&Vtl, g_Vtl);
    cudaGetSymbolAddress((void**)&S, g_S);
    cudaGetSymbolAddress((void**)&Ph, g_Ph);   cudaGetSymbolAddress((void**)&Pl, g_Pl);

    const size_t nX   = (size_t)MSEQ * DIM;
    const size_t strQ = (size_t)SEQ * DIM;
    const size_t strS = (size_t)SEQ * SEQ;
    const size_t strW = (size_t)DIM * DIM;

    // 1) split X; transpose+split W's
    split_k<<<4096, 256>>>(X, Xh, Xl, nX);
    {
        dim3 b(256), gW(DIM / 32, DIM / 32, 1);
        transpose_split_k<<<gW, b>>>(Wq, Wth + 0 * strW, Wtl + 0 * strW, DIM, DIM, 0, 0);
        transpose_split_k<<<gW, b>>>(Wk, Wth + 1 * strW, Wtl + 1 * strW, DIM, DIM, 0, 0);
        transpose_split_k<<<gW, b>>>(Wv, Wth + 2 * strW, Wtl + 2 * strW, DIM, DIM, 0, 0);
    }

    // 2) projections: M=16384, N=1024, K=1024
    {
        dim3 g(DIM / 256, MSEQ / 128, 1);
        gemm_mma<2><<<g, 512, GSMEM>>>(Xh, Xl, Wth + 0 * strW, Wtl + 0 * strW, bq, 1.0f,
                                       nullptr, Qh, Ql, DIM, DIM, 0, 0, 0);
        gemm_mma<2><<<g, 512, GSMEM>>>(Xh, Xl, Wth + 1 * strW, Wtl + 1 * strW, bk, 1.0f,
                                       nullptr, Kh, Kl, DIM, DIM, 0, 0, 0);
        gemm_mma<1><<<g, 512, GSMEM>>>(Xh, Xl, Wth + 2 * strW, Wtl + 2 * strW, bv, 1.0f,
                                       Vf, nullptr, nullptr, DIM, DIM, 0, 0, 0);
    }

    // 3) V^T split per batch: [4096 x 1024] -> [1024 x 4096]
    {
        dim3 b(256), gV(DIM / 32, SEQ / 32, BATCH);
        transpose_split_k<<<gV, b>>>(Vf, Vth, Vtl, SEQ, DIM, strQ, strQ);
    }

    // 4) scores: per batch S = Q*K^T / 32, M=N=4096, K=1024
    {
        dim3 g(SEQ / 256, SEQ / 128, BATCH);
        gemm_mma<0><<<g, 512, GSMEM>>>(Qh, Ql, Kh, Kl, nullptr, 1.0f / 32.0f,
                                       S, nullptr, nullptr, SEQ, DIM, strQ, strQ, strS);
    }

    // 5) softmax -> split P
    softmax_split_k<<<BATCH * SEQ, 256>>>(S, Ph, Pl);

    // 6) O = P*V: per batch M=4096, N=1024, K=4096
    {
        dim3 g(DIM / 256, SEQ / 128, BATCH);
        gemm_mma<0><<<g, 512, GSMEM>>>(Ph, Pl, Vth, Vtl, nullptr, 1.0f,
                                       O, nullptr, nullptr, DIM, SEQ, strS, strQ, strQ);
    }
}